// round 2
// baseline (speedup 1.0000x reference)
#include <cuda_runtime.h>
#include <math.h>

#define NB     8
#define CFEAT  384
#define CCODE  90
#define CPAD   96
#define HH     56
#define WW     56
#define SSD    32
#define SP     1024      // 32*32 spatial positions
#define NCOMBO 40        // 5 perms * 8 batch
#define HWIMG  (HH*WW)   // 3136

// ---------------- scratch (device globals; no allocation allowed) ----------------
__device__ float g_F1[NB][CFEAT*SP];       // normalized feats @ c1   [c][s]
__device__ float g_F2[NCOMBO][CFEAT*SP];   // normalized permuted feats @ c2
__device__ float g_LP[NB][CPAD*SP];        // log_softmax(code @ c1)  [c][s], pad zeros
__device__ float g_Q1[NB][CPAD*SP];        // exp(LP)                 pad zeros
__device__ float g_Q2[NCOMBO][CPAD*SP];    // softmax(code_neg @ c2)  pad zeros
__device__ float g_E1[NB][SP];             // entropy terms sum(q*lq)
__device__ float g_E2[NCOMBO][SP];
__device__ double g_acc[2];                // [0]=pos sum, [1]=neg sum

// ---------------- bilinear helper (border pad, align_corners=True) ----------------
struct BI { int o00,o01,o10,o11; float w00,w01,w10,w11; };

__device__ __forceinline__ BI bilinear(const float* __restrict__ crd) {
    float gx = (crd[0] + 1.0f) * 0.5f * (float)(WW-1);
    float gy = (crd[1] + 1.0f) * 0.5f * (float)(HH-1);
    gx = fminf(fmaxf(gx, 0.0f), (float)(WW-1));
    gy = fminf(fmaxf(gy, 0.0f), (float)(HH-1));
    float x0f = floorf(gx), y0f = floorf(gy);
    float wx = gx - x0f,   wy = gy - y0f;
    int x0 = (int)x0f, y0 = (int)y0f;
    int x1 = min(x0+1, WW-1), y1 = min(y0+1, HH-1);
    BI b;
    b.o00 = y0*WW + x0; b.o01 = y0*WW + x1;
    b.o10 = y1*WW + x0; b.o11 = y1*WW + x1;
    b.w00 = (1.0f-wx)*(1.0f-wy); b.w01 = wx*(1.0f-wy);
    b.w10 = (1.0f-wx)*wy;        b.w11 = wx*wy;
    return b;
}

// grid-sample feats for one (image, coord-set) and L2-normalize along channels
__device__ __forceinline__ void sample_norm_feats(const float* __restrict__ img,
                                                  const float* __restrict__ crd,
                                                  float* __restrict__ out, int s) {
    BI bi = bilinear(crd);
    float ss = 0.0f;
    #pragma unroll 4
    for (int c = 0; c < CFEAT; ++c) {
        const float* p = img + c*HWIMG;
        float v = bi.w00*p[bi.o00] + bi.w01*p[bi.o01] + bi.w10*p[bi.o10] + bi.w11*p[bi.o11];
        ss += v*v;
        out[c*SP + s] = v;
    }
    float sc = 1.0f / fmaxf(sqrtf(ss), 1e-10f);
    #pragma unroll 4
    for (int c = 0; c < CFEAT; ++c) out[c*SP + s] *= sc;
}

__device__ __forceinline__ void sample_code_raw(const float* __restrict__ img,
                                                const float* __restrict__ crd,
                                                float* __restrict__ out, int s) {
    BI bi = bilinear(crd);
    #pragma unroll 2
    for (int c = 0; c < CCODE; ++c) {
        const float* p = img + c*HWIMG;
        float v = bi.w00*p[bi.o00] + bi.w01*p[bi.o01] + bi.w10*p[bi.o10] + bi.w11*p[bi.o11];
        out[c*SP + s] = v;
    }
}

// ---------------- kernels ----------------
__global__ void k_init() { g_acc[0] = 0.0; g_acc[1] = 0.0; }

// A-side: 8 batches, coords1 transposed (output (a,b) uses coords1[n][b][a])
__global__ void k_sample_A(const float* __restrict__ feats,
                           const float* __restrict__ code,
                           const float* __restrict__ coords1) {
    int blk = blockIdx.x;            // 0..31
    int n = blk >> 2;
    int s = ((blk & 3) << 8) + threadIdx.x;
    int a = s >> 5, b = s & 31;
    const float* crd = coords1 + (((n*SSD + b)*SSD + a) << 1);
    sample_norm_feats(feats + (size_t)n*CFEAT*HWIMG, crd, g_F1[n], s);
    sample_code_raw (code  + (size_t)n*CCODE*HWIMG, crd, g_LP[n], s);
}

// B-side: 40 combos (perm k, batch i): image perms[k*8+i], coords2[i]
__global__ void k_sample_B(const float* __restrict__ feats,
                           const float* __restrict__ code,
                           const float* __restrict__ coords2,
                           const int*   __restrict__ perms) {
    int blk = blockIdx.x;            // 0..159
    int combo = blk >> 2;
    int i = combo & 7;
    int p = perms[combo];
    int s = ((blk & 3) << 8) + threadIdx.x;
    int a = s >> 5, b = s & 31;
    const float* crd = coords2 + (((i*SSD + b)*SSD + a) << 1);
    sample_norm_feats(feats + (size_t)p*CFEAT*HWIMG, crd, g_F2[combo], s);
    sample_code_raw (code  + (size_t)p*CCODE*HWIMG, crd, g_Q2[combo], s);
}

// column-wise log-softmax on raw code values; writes lp (optional), q, entropy
__device__ __forceinline__ void softmax_col(float* __restrict__ raw,  // in: raw, out: lp or q
                                            float* __restrict__ qout, // may equal raw
                                            float* __restrict__ entp,
                                            int s, bool keep_lp) {
    float m = -1e30f;
    for (int c = 0; c < CCODE; ++c) m = fmaxf(m, raw[c*SP + s]);
    float se = 0.0f;
    for (int c = 0; c < CCODE; ++c) se += expf(raw[c*SP + s] - m);
    float ls = m + logf(se);
    float ent = 0.0f;
    for (int c = 0; c < CCODE; ++c) {
        float l = raw[c*SP + s] - ls;
        float q = expf(l);
        ent += q * l;
        if (keep_lp) raw[c*SP + s] = l;
        qout[c*SP + s] = q;
    }
    for (int c = CCODE; c < CPAD; ++c) {              // zero pad channels
        if (keep_lp) raw[c*SP + s] = 0.0f;
        qout[c*SP + s] = 0.0f;
    }
    entp[s] = ent;
}

__global__ void k_softmax_A() {
    int blk = blockIdx.x; int n = blk >> 2;
    int s = ((blk & 3) << 8) + threadIdx.x;
    softmax_col(g_LP[n], g_Q1[n], g_E1[n], s, true);
}

__global__ void k_softmax_B() {
    int blk = blockIdx.x; int combo = blk >> 2;
    int s = ((blk & 3) << 8) + threadIdx.x;
    softmax_col(g_Q2[combo], g_Q2[combo], g_E2[combo], s, false);
}

// ---------------- fused dual-GEMM + epilogue + reduce ----------------
__device__ __forceinline__ void mm_acc(const float* __restrict__ A,
                                       const float* __restrict__ B,
                                       int Ktot, int m0, int n0,
                                       int tid, int tx, int ty,
                                       float acc[4][4],
                                       float (*As)[64], float (*Bs)[64]) {
    for (int k0 = 0; k0 < Ktot; k0 += 16) {
        #pragma unroll
        for (int r = 0; r < 4; ++r) {
            int e  = tid + (r << 8);
            int kr = e >> 6, cm = e & 63;
            As[kr][cm] = A[(k0 + kr)*SP + m0 + cm];
            Bs[kr][cm] = B[(k0 + kr)*SP + n0 + cm];
        }
        __syncthreads();
        #pragma unroll
        for (int kk = 0; kk < 16; ++kk) {
            float4 a = *(const float4*)&As[kk][tx << 2];
            float4 b = *(const float4*)&Bs[kk][ty << 2];
            float av[4] = {a.x, a.y, a.z, a.w};
            float bv[4] = {b.x, b.y, b.z, b.w};
            #pragma unroll
            for (int mi = 0; mi < 4; ++mi)
                #pragma unroll
                for (int jj = 0; jj < 4; ++jj)
                    acc[mi][jj] += av[mi] * bv[jj];
        }
        __syncthreads();
    }
}

__global__ void __launch_bounds__(256) k_gemm_loss() {
    __shared__ float As[16][64];
    __shared__ float Bs[16][64];
    __shared__ float red[8];

    int pair = blockIdx.z;
    int m0 = blockIdx.x * 64, n0 = blockIdx.y * 64;
    const float *Af, *Bf, *Alp, *Bq, *entp;
    if (pair < 8) {
        Af = g_F1[pair]; Bf = g_F1[pair];
        Alp = g_LP[pair]; Bq = g_Q1[pair]; entp = g_E1[pair];
    } else {
        int c = pair - 8; int i = c & 7;
        Af = g_F1[i]; Bf = g_F2[c];
        Alp = g_LP[i]; Bq = g_Q2[c]; entp = g_E2[c];
    }

    int tid = threadIdx.x;
    int tx = tid & 15, ty = tid >> 4;

    float fd[4][4], cr[4][4];
    #pragma unroll
    for (int i = 0; i < 4; ++i)
        #pragma unroll
        for (int j = 0; j < 4; ++j) { fd[i][j] = 0.0f; cr[i][j] = 0.0f; }

    mm_acc(Af,  Bf, CFEAT, m0, n0, tid, tx, ty, fd, As, Bs);  // cosine sim, K=384
    mm_acc(Alp, Bq, CPAD,  m0, n0, tid, tx, ty, cr, As, Bs);  // cross term, K=96

    float e[4];
    #pragma unroll
    for (int jj = 0; jj < 4; ++jj) e[jj] = entp[n0 + (ty << 2) + jj];

    // loss = (fd - cd)^2, cd = -tanh(0.5*(ent - cross - 1.1))
    float lsum = 0.0f;
    #pragma unroll
    for (int mi = 0; mi < 4; ++mi)
        #pragma unroll
        for (int jj = 0; jj < 4; ++jj) {
            float t = e[jj] - cr[mi][jj] - 1.1f;
            t = fminf(fmaxf(t, -30.0f), 30.0f);
            float u  = __expf(t);                       // tanh(t/2) = (e^t-1)/(e^t+1)
            float th = __fdividef(u - 1.0f, u + 1.0f);
            float d  = fd[mi][jj] + th;
            lsum += d * d;
        }

    // block reduce
    #pragma unroll
    for (int off = 16; off > 0; off >>= 1)
        lsum += __shfl_down_sync(0xffffffffu, lsum, off);
    if ((tid & 31) == 0) red[tid >> 5] = lsum;
    __syncthreads();
    if (tid == 0) {
        float tot = 0.0f;
        #pragma unroll
        for (int w = 0; w < 8; ++w) tot += red[w];
        atomicAdd(&g_acc[pair < 8 ? 0 : 1], (double)tot);
    }
}

__global__ void k_finalize(float* __restrict__ out) {
    out[0] = (float)(g_acc[0] / (double)(8.0  * 1024.0 * 1024.0 * 1024.0 / 1024.0 * 1024.0) );
    // careful: compute explicitly below instead
}

__global__ void k_finalize2(float* __restrict__ out) {
    out[0] = (float)(g_acc[0] / 8388608.0);    // 8  * 1024 * 1024
    out[1] = (float)(g_acc[1] / 41943040.0);   // 40 * 1024 * 1024
}

// ---------------- launch ----------------
extern "C" void kernel_launch(void* const* d_in, const int* in_sizes, int n_in,
                              void* d_out, int out_size) {
    const float* feats   = (const float*)d_in[0];
    const float* code    = (const float*)d_in[1];
    const float* coords1 = (const float*)d_in[2];
    const float* coords2 = (const float*)d_in[3];
    const int*   perms   = (const int*)  d_in[4];
    float* out = (float*)d_out;

    k_init<<<1, 1>>>();
    k_sample_A<<<32, 256>>>(feats, code, coords1);
    k_softmax_A<<<32, 256>>>();
    k_sample_B<<<160, 256>>>(feats, code, coords2, perms);
    k_softmax_B<<<160, 256>>>();
    dim3 g(16, 16, 48);
    k_gemm_loss<<<g, 256>>>();
    k_finalize2<<<1, 1>>>(out);
}

// round 3
// speedup vs baseline: 2.4021x; 2.4021x over previous
#include <cuda_runtime.h>
#include <cuda_bf16.h>
#include <math.h>

#define NB     8
#define CFEAT  384
#define CCODE  90
#define CPAD   96
#define HH     56
#define WW     56
#define SSD    32
#define SP     1024
#define NCOMBO 40
#define HWIMG  3136
#define KF     (CFEAT*3)   // 1152 : [Ah|Ah|Al] vs [Bh|Bl|Bh]
#define KC     (CPAD*3)    // 288
#define SROW   40          // smem row stride (bf16) -> conflict-free frag loads

// ---------------- scratch ----------------
__device__ float g_featsT[NB][HWIMG*CFEAT];        // [n][pixel][c]
__device__ float g_codeT[NB][HWIMG*CPAD];          // [n][pixel][c] zero-padded 90->96
__device__ __nv_bfloat16 g_FA[NB][SP*KF];          // A-form feats  [s][k]
__device__ __nv_bfloat16 g_FB[NB][SP*KF];          // B-form feats
__device__ __nv_bfloat16 g_F2B[NCOMBO][SP*KF];     // B-form permuted feats
__device__ __nv_bfloat16 g_LPA[NB][SP*KC];         // A-form log-probs
__device__ __nv_bfloat16 g_QB[NB][SP*KC];          // B-form probs
__device__ __nv_bfloat16 g_Q2B[NCOMBO][SP*KC];     // B-form permuted probs
__device__ float g_E1[NB][SP];
__device__ float g_E2[NCOMBO][SP];
__device__ double g_acc[2];

// ---------------- init ----------------
__global__ void k_init() { g_acc[0] = 0.0; g_acc[1] = 0.0; }

// ---------------- transposes: [c][p] -> [p][c] ----------------
__global__ void k_transpose_f(const float* __restrict__ in) {
    __shared__ float tile[32][33];
    int n = blockIdx.x, pz = blockIdx.y, cz = blockIdx.z;
    int tx = threadIdx.x, ty = threadIdx.y;           // 32 x 8
    const float* src = in + (size_t)n*CFEAT*HWIMG;
    #pragma unroll
    for (int j = 0; j < 4; ++j) {
        int c = cz*32 + ty + j*8;
        int p = pz*32 + tx;
        tile[ty + j*8][tx] = src[(size_t)c*HWIMG + p];
    }
    __syncthreads();
    float* dst = g_featsT[n];
    #pragma unroll
    for (int j = 0; j < 4; ++j) {
        int p = pz*32 + ty + j*8;
        int c = cz*32 + tx;
        dst[(size_t)p*CFEAT + c] = tile[tx][ty + j*8];
    }
}

__global__ void k_transpose_c(const float* __restrict__ in) {
    __shared__ float tile[32][33];
    int n = blockIdx.x, pz = blockIdx.y, cz = blockIdx.z;
    int tx = threadIdx.x, ty = threadIdx.y;
    const float* src = in + (size_t)n*CCODE*HWIMG;
    #pragma unroll
    for (int j = 0; j < 4; ++j) {
        int c = cz*32 + ty + j*8;
        int p = pz*32 + tx;
        tile[ty + j*8][tx] = (c < CCODE) ? src[(size_t)c*HWIMG + p] : 0.0f;
    }
    __syncthreads();
    float* dst = g_codeT[n];
    #pragma unroll
    for (int j = 0; j < 4; ++j) {
        int p = pz*32 + ty + j*8;
        int c = cz*32 + tx;
        dst[(size_t)p*CPAD + c] = tile[tx][ty + j*8];
    }
}

// ---------------- bilinear ----------------
struct BI { int o00,o01,o10,o11; float w00,w01,w10,w11; };

__device__ __forceinline__ BI bilinear(const float* __restrict__ crd) {
    float gx = (crd[0] + 1.0f) * 0.5f * (float)(WW-1);
    float gy = (crd[1] + 1.0f) * 0.5f * (float)(HH-1);
    gx = fminf(fmaxf(gx, 0.0f), (float)(WW-1));
    gy = fminf(fmaxf(gy, 0.0f), (float)(HH-1));
    float x0f = floorf(gx), y0f = floorf(gy);
    float wx = gx - x0f,   wy = gy - y0f;
    int x0 = (int)x0f, y0 = (int)y0f;
    int x1 = min(x0+1, WW-1), y1 = min(y0+1, HH-1);
    BI b;
    b.o00 = y0*WW + x0; b.o01 = y0*WW + x1;
    b.o10 = y1*WW + x0; b.o11 = y1*WW + x1;
    b.w00 = (1.0f-wx)*(1.0f-wy); b.w01 = wx*(1.0f-wy);
    b.w10 = (1.0f-wx)*wy;        b.w11 = wx*wy;
    return b;
}

__device__ __forceinline__ __nv_bfloat16 bhi(float v) { return __float2bfloat16(v); }

// warp-per-position sampling core; writes feats (A and/or B form) + code (lp/q)
__device__ __forceinline__ void sample_warp(
    int img, const float* __restrict__ crd, int lane,
    __nv_bfloat16* __restrict__ fa,   // may be null
    __nv_bfloat16* __restrict__ fb,
    __nv_bfloat16* __restrict__ lpA,  // may be null
    __nv_bfloat16* __restrict__ qB,
    float* __restrict__ entOut)
{
    BI bi = bilinear(crd);
    const float* T = g_featsT[img];
    const float* p00 = T + (size_t)bi.o00*CFEAT;
    const float* p01 = T + (size_t)bi.o01*CFEAT;
    const float* p10 = T + (size_t)bi.o10*CFEAT;
    const float* p11 = T + (size_t)bi.o11*CFEAT;

    float v[12]; float ss = 0.0f;
    #pragma unroll
    for (int j = 0; j < 12; ++j) {
        int c = lane + 32*j;
        float x = bi.w00*p00[c] + bi.w01*p01[c] + bi.w10*p10[c] + bi.w11*p11[c];
        v[j] = x; ss += x*x;
    }
    #pragma unroll
    for (int o = 16; o; o >>= 1) ss += __shfl_xor_sync(0xffffffffu, ss, o);
    float sc = 1.0f / fmaxf(sqrtf(ss), 1e-10f);

    #pragma unroll
    for (int j = 0; j < 12; ++j) {
        int c = lane + 32*j;
        float x = v[j] * sc;
        __nv_bfloat16 h = bhi(x);
        __nv_bfloat16 l = bhi(x - __bfloat162float(h));
        if (fa) { fa[c] = h; fa[CFEAT+c] = h; fa[2*CFEAT+c] = l; }
        fb[c] = h; fb[CFEAT+c] = l; fb[2*CFEAT+c] = h;
    }

    // code softmax (channels across lanes: c = lane, lane+32, lane+64)
    const float* C = g_codeT[img];
    const float* q00 = C + (size_t)bi.o00*CPAD;
    const float* q01 = C + (size_t)bi.o01*CPAD;
    const float* q10 = C + (size_t)bi.o10*CPAD;
    const float* q11 = C + (size_t)bi.o11*CPAD;
    float r[3];
    #pragma unroll
    for (int j = 0; j < 3; ++j) {
        int c = lane + 32*j;
        r[j] = (c < CCODE) ? (bi.w00*q00[c] + bi.w01*q01[c] + bi.w10*q10[c] + bi.w11*q11[c])
                           : -INFINITY;
    }
    float m = fmaxf(fmaxf(r[0], r[1]), r[2]);
    #pragma unroll
    for (int o = 16; o; o >>= 1) m = fmaxf(m, __shfl_xor_sync(0xffffffffu, m, o));
    float se = 0.0f;
    #pragma unroll
    for (int j = 0; j < 3; ++j) se += expf(r[j] - m);   // exp(-inf)=0 for pads
    #pragma unroll
    for (int o = 16; o; o >>= 1) se += __shfl_xor_sync(0xffffffffu, se, o);
    float ls = m + logf(se);

    float ent = 0.0f;
    __nv_bfloat16 z = bhi(0.0f);
    #pragma unroll
    for (int j = 0; j < 3; ++j) {
        int c = lane + 32*j;
        if (c < CCODE) {
            float lp = r[j] - ls;
            float q  = expf(lp);
            ent += q * lp;
            __nv_bfloat16 lh = bhi(lp);
            __nv_bfloat16 ll = bhi(lp - __bfloat162float(lh));
            __nv_bfloat16 qh = bhi(q);
            __nv_bfloat16 ql = bhi(q - __bfloat162float(qh));
            if (lpA) { lpA[c] = lh; lpA[CPAD+c] = lh; lpA[2*CPAD+c] = ll; }
            qB[c] = qh; qB[CPAD+c] = ql; qB[2*CPAD+c] = qh;
        } else {
            if (lpA) { lpA[c] = z; lpA[CPAD+c] = z; lpA[2*CPAD+c] = z; }
            qB[c] = z; qB[CPAD+c] = z; qB[2*CPAD+c] = z;
        }
    }
    #pragma unroll
    for (int o = 16; o; o >>= 1) ent += __shfl_xor_sync(0xffffffffu, ent, o);
    if (lane == 0) *entOut = ent;
}

__global__ void __launch_bounds__(256) k_sample_A(const float* __restrict__ coords1) {
    int n = blockIdx.x;
    int warp = threadIdx.x >> 5, lane = threadIdx.x & 31;
    int s = blockIdx.y * 8 + warp;
    int a = s >> 5, b = s & 31;
    const float* crd = coords1 + (((n*SSD + b)*SSD + a) << 1);
    sample_warp(n, crd, lane,
                g_FA[n]  + (size_t)s*KF,
                g_FB[n]  + (size_t)s*KF,
                g_LPA[n] + (size_t)s*KC,
                g_QB[n]  + (size_t)s*KC,
                &g_E1[n][s]);
}

__global__ void __launch_bounds__(256) k_sample_B(const float* __restrict__ coords2,
                                                  const int* __restrict__ perms) {
    int combo = blockIdx.x;
    int i = combo & 7;
    int p = perms[combo];
    int warp = threadIdx.x >> 5, lane = threadIdx.x & 31;
    int s = blockIdx.y * 8 + warp;
    int a = s >> 5, b = s & 31;
    const float* crd = coords2 + (((i*SSD + b)*SSD + a) << 1);
    sample_warp(p, crd, lane,
                (__nv_bfloat16*)nullptr,
                g_F2B[combo] + (size_t)s*KF,
                (__nv_bfloat16*)nullptr,
                g_Q2B[combo] + (size_t)s*KC,
                &g_E2[combo][s]);
}

// ---------------- tensor-core GEMM + fused loss ----------------
__device__ __forceinline__ void cp16(void* sm, const void* gm) {
    unsigned a = (unsigned)__cvta_generic_to_shared(sm);
    asm volatile("cp.async.cg.shared.global [%0], [%1], 16;\n" :: "r"(a), "l"(gm));
}
__device__ __forceinline__ void cp_commit() { asm volatile("cp.async.commit_group;\n"); }
__device__ __forceinline__ void cp_wait1()  { asm volatile("cp.async.wait_group 1;\n"); }
__device__ __forceinline__ void cp_wait0()  { asm volatile("cp.async.wait_group 0;\n"); }

__device__ __forceinline__ void mma_bf16(float* d, unsigned a0, unsigned a1, unsigned a2, unsigned a3,
                                         unsigned b0, unsigned b1) {
    asm volatile(
        "mma.sync.aligned.m16n8k16.row.col.f32.bf16.bf16.f32 "
        "{%0,%1,%2,%3},{%4,%5,%6,%7},{%8,%9},{%0,%1,%2,%3};\n"
        : "+f"(d[0]), "+f"(d[1]), "+f"(d[2]), "+f"(d[3])
        : "r"(a0), "r"(a1), "r"(a2), "r"(a3), "r"(b0), "r"(b1));
}

__device__ __forceinline__ void load_stage(__nv_bfloat16 (*sA)[SROW], __nv_bfloat16 (*sB)[SROW],
                                           const __nv_bfloat16* __restrict__ Ag,
                                           const __nv_bfloat16* __restrict__ Bg,
                                           int Kt, int k0, int tid) {
    #pragma unroll
    for (int j = 0; j < 2; ++j) {
        int chunk = tid + j*256;
        int row = chunk >> 2, q = chunk & 3;
        cp16(&sA[row][q*8], Ag + (size_t)row*Kt + k0 + q*8);
        cp16(&sB[row][q*8], Bg + (size_t)row*Kt + k0 + q*8);
    }
    cp_commit();
}

__device__ __forceinline__ void gemm_pass(float acc[2][8][4],
                                          const __nv_bfloat16* __restrict__ Ag,
                                          const __nv_bfloat16* __restrict__ Bg,
                                          int Kt,
                                          __nv_bfloat16 (*sA)[128][SROW],
                                          __nv_bfloat16 (*sB)[128][SROW]) {
    int tid  = threadIdx.x;
    int warp = tid >> 5, lane = tid & 31;
    int g = lane >> 2, tg = lane & 3;
    int wm = (warp & 3) * 32;     // warp tile 32(m) x 64(n)
    int wn = (warp >> 2) * 64;
    int stages = Kt / 32;
    load_stage(sA[0], sB[0], Ag, Bg, Kt, 0, tid);
    int buf = 0;
    for (int st = 0; st < stages; ++st) {
        if (st + 1 < stages) { load_stage(sA[buf^1], sB[buf^1], Ag, Bg, Kt, (st+1)*32, tid); cp_wait1(); }
        else                 { cp_wait0(); }
        __syncthreads();
        #pragma unroll
        for (int kk = 0; kk < 32; kk += 16) {
            unsigned a[2][4];
            #pragma unroll
            for (int mi = 0; mi < 2; ++mi) {
                int r0 = wm + mi*16 + g;
                a[mi][0] = *(const unsigned*)&sA[buf][r0    ][kk + 2*tg    ];
                a[mi][1] = *(const unsigned*)&sA[buf][r0 + 8][kk + 2*tg    ];
                a[mi][2] = *(const unsigned*)&sA[buf][r0    ][kk + 2*tg + 8];
                a[mi][3] = *(const unsigned*)&sA[buf][r0 + 8][kk + 2*tg + 8];
            }
            #pragma unroll
            for (int ni = 0; ni < 8; ++ni) {
                int rb = wn + ni*8 + g;
                unsigned b0 = *(const unsigned*)&sB[buf][rb][kk + 2*tg    ];
                unsigned b1 = *(const unsigned*)&sB[buf][rb][kk + 2*tg + 8];
                mma_bf16(acc[0][ni], a[0][0], a[0][1], a[0][2], a[0][3], b0, b1);
                mma_bf16(acc[1][ni], a[1][0], a[1][1], a[1][2], a[1][3], b0, b1);
            }
        }
        __syncthreads();
        buf ^= 1;
    }
}

__global__ void __launch_bounds__(256) k_gemm_loss() {
    __shared__ __nv_bfloat16 sA[2][128][SROW];
    __shared__ __nv_bfloat16 sB[2][128][SROW];
    __shared__ float red[8];

    int pair = blockIdx.z;
    const __nv_bfloat16 *Af, *Bf, *Ac, *Bc;
    const float* ent;
    if (pair < 8) {
        Af = g_FA[pair]; Bf = g_FB[pair];
        Ac = g_LPA[pair]; Bc = g_QB[pair]; ent = g_E1[pair];
    } else {
        int c = pair - 8, i = c & 7;
        Af = g_FA[i]; Bf = g_F2B[c];
        Ac = g_LPA[i]; Bc = g_Q2B[c]; ent = g_E2[c];
    }
    int m0 = blockIdx.x * 128, n0 = blockIdx.y * 128;
    Af += (size_t)m0*KF;  Bf += (size_t)n0*KF;
    Ac += (size_t)m0*KC;  Bc += (size_t)n0*KC;

    float fd[2][8][4] = {};
    float cr[2][8][4] = {};
    gemm_pass(cr, Ac, Bc, KC, sA, sB);   // cross term  K=288
    gemm_pass(fd, Af, Bf, KF, sA, sB);   // cosine sim  K=1152

    int tid = threadIdx.x;
    int warp = tid >> 5, lane = tid & 31;
    int g = lane >> 2, tg = lane & 3;
    int wn = (warp >> 2) * 64;

    float lsum = 0.0f;
    #pragma unroll
    for (int ni = 0; ni < 8; ++ni) {
        int ncol = n0 + wn + ni*8 + 2*tg;
        float e0 = ent[ncol], e1 = ent[ncol + 1];
        #pragma unroll
        for (int mi = 0; mi < 2; ++mi) {
            #pragma unroll
            for (int r = 0; r < 4; ++r) {
                float e = (r & 1) ? e1 : e0;
                float t = e - cr[mi][ni][r] - 1.1f;
                t = fminf(fmaxf(t, -30.0f), 30.0f);
                float u  = __expf(t);
                float th = __fdividef(u - 1.0f, u + 1.0f);    // tanh(t/2)
                float d  = fd[mi][ni][r] + th;
                lsum += d * d;
            }
        }
    }

    #pragma unroll
    for (int off = 16; off > 0; off >>= 1)
        lsum += __shfl_down_sync(0xffffffffu, lsum, off);
    if (lane == 0) red[warp] = lsum;
    __syncthreads();
    if (tid == 0) {
        float tot = 0.0f;
        #pragma unroll
        for (int w = 0; w < 8; ++w) tot += red[w];
        atomicAdd(&g_acc[pair < 8 ? 0 : 1], (double)tot);
    }
}

__global__ void k_finalize(float* __restrict__ out) {
    out[0] = (float)(g_acc[0] / 8388608.0);    // 8  * 1024 * 1024
    out[1] = (float)(g_acc[1] / 41943040.0);   // 40 * 1024 * 1024
}

// ---------------- launch ----------------
extern "C" void kernel_launch(void* const* d_in, const int* in_sizes, int n_in,
                              void* d_out, int out_size) {
    const float* feats   = (const float*)d_in[0];
    const float* code    = (const float*)d_in[1];
    const float* coords1 = (const float*)d_in[2];
    const float* coords2 = (const float*)d_in[3];
    const int*   perms   = (const int*)  d_in[4];
    float* out = (float*)d_out;

    k_init<<<1, 1>>>();
    k_transpose_f<<<dim3(NB, 98, 12), dim3(32, 8)>>>(feats);
    k_transpose_c<<<dim3(NB, 98, 3),  dim3(32, 8)>>>(code);
    k_sample_A<<<dim3(NB, 128), 256>>>(coords1);
    k_sample_B<<<dim3(NCOMBO, 128), 256>>>(coords2, perms);
    k_gemm_loss<<<dim3(8, 8, 48), 256>>>();
    k_finalize<<<1, 1>>>(out);
}